// round 1
// baseline (speedup 1.0000x reference)
#include <cuda_runtime.h>
#include <cuda_bf16.h>
#include <math.h>

// Problem constants
#define PB 2
#define PT 2048
#define PE 1024
#define PH 16
#define PD 64
#define PV 32000
#define PM (PB*PT)          // 4096 rows
#define BTV ((size_t)PM*PV) // logits element count

// ---------------- scratch (__device__ globals; no allocation) ----------------
__device__ float g_x[PM*PE];   // embedded input [M, E]
__device__ float g_q[PM*PE];   // [B,H,T,D]
__device__ float g_k[PM*PE];   // [B,H,T,D]
__device__ float g_v[PM*PE];   // [B,H,T,D]
__device__ float g_o[PM*PE];   // attention out [M, E] (heads concat)
__device__ float g_rowloss[PM];

// ---------------- embed: x = tok_table[tokens] + pos_emb ----------------
__global__ void embed_kernel(const int* __restrict__ tokens,
                             const float* __restrict__ tok_table,
                             const float* __restrict__ pos_emb,
                             float* __restrict__ x)
{
    int idx = blockIdx.x * blockDim.x + threadIdx.x; // over M*E
    int row = idx >> 10;         // / E
    int e   = idx & (PE - 1);
    int t   = row & (PT - 1);
    int tok = tokens[row];
    x[idx] = tok_table[(size_t)tok * PE + e] + pos_emb[(size_t)t * PE + e];
}

// ---------------- NT SGEMM: C[m,n] = sum_k A[m,k] * Bw[n,k] + bias[n] ----------------
// M=4096 fixed, K=1024 fixed, N runtime (1024 or 32000), all multiples of tile sizes.
// permute==1: write to [B,H,T,D] layout (for q/k/v), else plain [M,N].
#define GBM 128
#define GBN 128
#define GBK 16
__global__ __launch_bounds__(256)
void gemm_nt(const float* __restrict__ A, const float* __restrict__ Bw,
             const float* __restrict__ bias, float* __restrict__ C,
             int N, int permute)
{
    __shared__ float As[GBK][GBM];
    __shared__ float Bs[GBK][GBN];
    const int K = PE; // 1024
    int tid = threadIdx.x;
    int bm = blockIdx.y, bn = blockIdx.x;
    const float* Ab = A  + (size_t)bm * GBM * K;
    const float* Bb = Bw + (size_t)bn * GBN * K;
    int tr = tid >> 4;   // 0..15
    int tc = tid & 15;   // 0..15

    float acc[8][8];
#pragma unroll
    for (int i = 0; i < 8; i++)
#pragma unroll
        for (int j = 0; j < 8; j++) acc[i][j] = 0.f;

    for (int kt = 0; kt < K; kt += GBK) {
#pragma unroll
        for (int i = 0; i < 2; i++) {
            int f   = tid + i * 256;     // 0..511 float4 slots
            int row = f >> 2;            // 0..127
            int kc  = (f & 3) << 2;      // 0,4,8,12
            float4 av = *(const float4*)(Ab + (size_t)row * K + kt + kc);
            As[kc+0][row] = av.x; As[kc+1][row] = av.y;
            As[kc+2][row] = av.z; As[kc+3][row] = av.w;
            float4 bv = *(const float4*)(Bb + (size_t)row * K + kt + kc);
            Bs[kc+0][row] = bv.x; Bs[kc+1][row] = bv.y;
            Bs[kc+2][row] = bv.z; Bs[kc+3][row] = bv.w;
        }
        __syncthreads();
#pragma unroll
        for (int kk = 0; kk < GBK; kk++) {
            float a[8], b[8];
            *(float4*)(a)     = *(float4*)&As[kk][tr*8];
            *(float4*)(a + 4) = *(float4*)&As[kk][tr*8 + 4];
            *(float4*)(b)     = *(float4*)&Bs[kk][tc*8];
            *(float4*)(b + 4) = *(float4*)&Bs[kk][tc*8 + 4];
#pragma unroll
            for (int i = 0; i < 8; i++)
#pragma unroll
                for (int j = 0; j < 8; j++)
                    acc[i][j] += a[i] * b[j];
        }
        __syncthreads();
    }

#pragma unroll
    for (int i = 0; i < 8; i++) {
        int m = bm * GBM + tr * 8 + i;
#pragma unroll
        for (int j = 0; j < 8; j++) {
            int n = bn * GBN + tc * 8 + j;
            float val = acc[i][j] + bias[n];
            if (!permute) {
                C[(size_t)m * N + n] = val;
            } else {
                // m = b*T + t ; n = h*D + d  -> [B,H,T,D]
                int b = m >> 11, t = m & (PT - 1);
                int h = n >> 6,  d = n & (PD - 1);
                C[((((size_t)b * PH + h) * PT) + t) * PD + d] = val;
            }
        }
    }
}

// ---------------- attention: flash-style online softmax ----------------
// Faithful quirk: score = (s<=t) ? dot : 0 ; then w==0 -> -inf ; softmax ; /sqrt(D)
#define AT_BQ 128
#define AT_BS 64
__global__ __launch_bounds__(128)
void attn_kernel(const float* __restrict__ q, const float* __restrict__ k,
                 const float* __restrict__ v, float* __restrict__ o)
{
    __shared__ float Ks[AT_BS][PD];
    __shared__ float Vs[AT_BS][PD];
    int bh = blockIdx.y;                    // 0..31 (b*H+h)
    int tq = blockIdx.x * AT_BQ + threadIdx.x; // query index t in [0,2048)
    int b  = bh >> 4, h = bh & 15;

    const float* qb = q + (size_t)bh * PT * PD;
    const float* kb = k + (size_t)bh * PT * PD;
    const float* vb = v + (size_t)bh * PT * PD;

    float qreg[PD];
    {
        const float4* qr = (const float4*)(qb + (size_t)tq * PD);
#pragma unroll
        for (int i = 0; i < 16; i++) {
            float4 tv = qr[i];
            qreg[4*i+0]=tv.x; qreg[4*i+1]=tv.y; qreg[4*i+2]=tv.z; qreg[4*i+3]=tv.w;
        }
    }
    float m = -INFINITY, l = 0.f;
    float acc[PD];
#pragma unroll
    for (int d = 0; d < PD; d++) acc[d] = 0.f;

    int send = blockIdx.x * AT_BQ + AT_BQ - 1; // last query row in this block
    for (int s0 = 0; s0 <= send; s0 += AT_BS) {
        // tile is contiguous (s contiguous in [B,H,T,D])
        const float4* ksrc = (const float4*)(kb + (size_t)s0 * PD);
        const float4* vsrc = (const float4*)(vb + (size_t)s0 * PD);
        float4* kdst = (float4*)&Ks[0][0];
        float4* vdst = (float4*)&Vs[0][0];
#pragma unroll
        for (int i = 0; i < 8; i++) {
            int f = threadIdx.x + i * 128; // 1024 float4 per tile
            kdst[f] = ksrc[f];
            vdst[f] = vsrc[f];
        }
        __syncthreads();

        int smax = tq - s0 + 1;
        if (smax > AT_BS) smax = AT_BS;
        for (int s = 0; s < smax; s++) {
            float dot = 0.f;
            const float4* kr = (const float4*)Ks[s];
#pragma unroll
            for (int i = 0; i < 16; i++) {
                float4 kv = kr[i];
                dot += qreg[4*i+0]*kv.x + qreg[4*i+1]*kv.y
                     + qreg[4*i+2]*kv.z + qreg[4*i+3]*kv.w;
            }
            if (dot == 0.0f) continue;   // masked_fill(w==0, -inf) quirk -> p=0
            if (dot > m) {
                float c = __expf(m - dot);  // m=-inf -> c=0, zeroes history
                l *= c;
#pragma unroll
                for (int d = 0; d < PD; d++) acc[d] *= c;
                m = dot;
            }
            float p = __expf(dot - m);
            l += p;
            const float4* vr = (const float4*)Vs[s];
#pragma unroll
            for (int i = 0; i < 16; i++) {
                float4 vv = vr[i];
                acc[4*i+0] += p * vv.x; acc[4*i+1] += p * vv.y;
                acc[4*i+2] += p * vv.z; acc[4*i+3] += p * vv.w;
            }
        }
        __syncthreads();
    }

    // o row = b*T + tq, cols [h*D, h*D+64) ; post-softmax scale 1/sqrt(D)=1/8
    float inv = 1.f / (l * 8.0f);
    float* orow = o + ((size_t)(b * PT + tq)) * PE + h * PD;
#pragma unroll
    for (int i = 0; i < 16; i++) {
        float4 ov;
        ov.x = acc[4*i+0]*inv; ov.y = acc[4*i+1]*inv;
        ov.z = acc[4*i+2]*inv; ov.w = acc[4*i+3]*inv;
        ((float4*)orow)[i] = ov;
    }
}

// ---------------- loss ----------------
__global__ __launch_bounds__(256)
void rowloss_kernel(const float* __restrict__ logits, const int* __restrict__ targets,
                    float* __restrict__ rowloss)
{
    __shared__ float red[256];
    int row = blockIdx.x;
    int tid = threadIdx.x;
    const float* lr = logits + (size_t)row * PV;

    float mx = -INFINITY;
    for (int c = tid; c < PV; c += 256) mx = fmaxf(mx, lr[c]);
    red[tid] = mx; __syncthreads();
    for (int s = 128; s > 0; s >>= 1) {
        if (tid < s) red[tid] = fmaxf(red[tid], red[tid + s]);
        __syncthreads();
    }
    mx = red[0]; __syncthreads();

    float se = 0.f;
    for (int c = tid; c < PV; c += 256) se += expf(lr[c] - mx);
    red[tid] = se; __syncthreads();
    for (int s = 128; s > 0; s >>= 1) {
        if (tid < s) red[tid] += red[tid + s];
        __syncthreads();
    }
    if (tid == 0) {
        float lse = mx + logf(red[0]);
        rowloss[row] = -(lr[targets[row]] - lse);
    }
}

__global__ __launch_bounds__(256)
void finloss_kernel(const float* __restrict__ rowloss, float* __restrict__ out_loss)
{
    __shared__ float red[256];
    int tid = threadIdx.x;
    float s = 0.f;
    for (int i = tid; i < PM; i += 256) s += rowloss[i];
    red[tid] = s; __syncthreads();
    for (int k = 128; k > 0; k >>= 1) {
        if (tid < k) red[tid] += red[tid + k];
        __syncthreads();
    }
    if (tid == 0) out_loss[0] = red[0] / (float)PM;
}

// ---------------- launch ----------------
extern "C" void kernel_launch(void* const* d_in, const int* in_sizes, int n_in,
                              void* d_out, int out_size)
{
    const int*   tokens    = (const int*)d_in[0];
    const int*   targets   = (const int*)d_in[1];
    const float* tok_table = (const float*)d_in[2];
    const float* pos_emb   = (const float*)d_in[3];
    const float* Wq = (const float*)d_in[4];  const float* bq = (const float*)d_in[5];
    const float* Wk = (const float*)d_in[6];  const float* bk = (const float*)d_in[7];
    const float* Wv = (const float*)d_in[8];  const float* bv = (const float*)d_in[9];
    const float* Wo = (const float*)d_in[10]; const float* bo = (const float*)d_in[11];
    float* out = (float*)d_out;

    float *x, *q, *k, *v, *o, *rl;
    cudaGetSymbolAddress((void**)&x,  g_x);
    cudaGetSymbolAddress((void**)&q,  g_q);
    cudaGetSymbolAddress((void**)&k,  g_k);
    cudaGetSymbolAddress((void**)&v,  g_v);
    cudaGetSymbolAddress((void**)&o,  g_o);
    cudaGetSymbolAddress((void**)&rl, g_rowloss);

    // 1) embedding
    embed_kernel<<<(PM * PE) / 256, 256>>>(tokens, tok_table, pos_emb, x);

    // 2) QKV projections (NT gemm, permuted epilogue to [B,H,T,D])
    dim3 gqkv(PE / GBN, PM / GBM);     // (8, 32)
    gemm_nt<<<gqkv, 256>>>(x, Wq, bq, q, PE, 1);
    gemm_nt<<<gqkv, 256>>>(x, Wk, bk, k, PE, 1);
    gemm_nt<<<gqkv, 256>>>(x, Wv, bv, v, PE, 1);

    // 3) attention
    dim3 gat(PT / AT_BQ, PB * PH);     // (16, 32)
    attn_kernel<<<gat, AT_BQ>>>(q, k, v, o);

    // 4) logits GEMM -> d_out
    dim3 glog(PV / GBN, PM / GBM);     // (250, 32)
    gemm_nt<<<glog, 256>>>(o, Wo, bo, out, PV, 0);

    // 5) loss (written after logits, if output has room for it)
    if ((size_t)out_size > BTV) {
        rowloss_kernel<<<PM, 256>>>(out, targets, rl);
        finloss_kernel<<<1, 256>>>(rl, out + BTV);
    }
}

// round 3
// speedup vs baseline: 1.3045x; 1.3045x over previous
#include <cuda_runtime.h>
#include <cuda_bf16.h>
#include <math.h>
#include <cstdint>

// ---------------- problem constants ----------------
#define PB 2
#define PT 2048
#define PE 1024
#define PH 16
#define PD 64
#define PV 32000
#define PM (PB*PT)            // 4096
#define QKVN 3072
#define KP 3072               // K' = 3*E (precision-split concat)
#define BTV ((size_t)PM*PV)

// ---------------- scratch (__device__ globals) ----------------
__device__ __nv_bfloat16 g_xp[(size_t)PM*KP];       // x'  = [xh|xh|xl]
__device__ __nv_bfloat16 g_wqkv[(size_t)QKVN*KP];   // Wqkv' = [Wh|Wl|Wh]
__device__ __nv_bfloat16 g_wop[(size_t)PV*KP];      // Wo' = [Woh|Wol|Woh]
__device__ __nv_bfloat16 g_op[(size_t)PM*KP];       // o'  = [oh|oh|ol]
__device__ float g_qkv[(size_t)PM*QKVN];            // fused qkv out (fp32)
__device__ float g_bias3[QKVN];
__device__ float g_rowloss[PM];

// ---------------- helpers ----------------
__device__ __forceinline__ uint32_t smem_u32(const void* p) {
    uint32_t a;
    asm("{ .reg .u64 t; cvta.to.shared.u64 t, %1; cvt.u32.u64 %0, t; }" : "=r"(a) : "l"(p));
    return a;
}
__device__ __forceinline__ void cp16(uint32_t dst, const void* src) {
    asm volatile("cp.async.cg.shared.global [%0], [%1], 16;" :: "r"(dst), "l"(src) : "memory");
}
#define CP_COMMIT() asm volatile("cp.async.commit_group;" ::: "memory")
#define CP_WAIT(n)  asm volatile("cp.async.wait_group %0;" :: "n"(n) : "memory")

#define LDSM4(r0,r1,r2,r3,addr) \
    asm volatile("ldmatrix.sync.aligned.m8n8.x4.shared.b16 {%0,%1,%2,%3}, [%4];" \
        : "=r"(r0),"=r"(r1),"=r"(r2),"=r"(r3) : "r"(addr))

#define MMA16816(c, a, b0, b1) \
    asm volatile("mma.sync.aligned.m16n8k16.row.col.f32.bf16.bf16.f32 " \
        "{%0,%1,%2,%3}, {%4,%5,%6,%7}, {%8,%9}, {%0,%1,%2,%3};" \
        : "+f"((c)[0]), "+f"((c)[1]), "+f"((c)[2]), "+f"((c)[3]) \
        : "r"((a)[0]), "r"((a)[1]), "r"((a)[2]), "r"((a)[3]), "r"(b0), "r"(b1))

// ---------------- split/pack kernels ----------------
__global__ void embed_split(const int* __restrict__ tokens,
                            const float* __restrict__ tok_table,
                            const float* __restrict__ pos_emb,
                            __nv_bfloat16* __restrict__ xp)
{
    int idx = blockIdx.x * blockDim.x + threadIdx.x; // over M*E
    int row = idx >> 10, e = idx & (PE - 1);
    int t = row & (PT - 1);
    float v = tok_table[(size_t)tokens[row] * PE + e] + pos_emb[(size_t)t * PE + e];
    __nv_bfloat16 h = __float2bfloat16(v);
    __nv_bfloat16 l = __float2bfloat16(v - __bfloat162float(h));
    size_t base = (size_t)row * KP + e;
    xp[base] = h; xp[base + 1024] = h; xp[base + 2048] = l;   // A-layout [h|h|l]
}

// B-side split: dst row-major KP stride, [h | l | h]
__global__ void splitB(const float* __restrict__ src, __nv_bfloat16* __restrict__ dst, int n)
{
    int idx = blockIdx.x * blockDim.x + threadIdx.x;
    if (idx >= n) return;
    int row = idx >> 10, c = idx & (PE - 1);
    float v = src[idx];
    __nv_bfloat16 h = __float2bfloat16(v);
    __nv_bfloat16 l = __float2bfloat16(v - __bfloat162float(h));
    size_t base = (size_t)row * KP + c;
    dst[base] = h; dst[base + 1024] = l; dst[base + 2048] = h;
}

__global__ void pack_bias(const float* __restrict__ bq, const float* __restrict__ bk,
                          const float* __restrict__ bv, float* __restrict__ b3)
{
    int i = blockIdx.x * blockDim.x + threadIdx.x;
    if (i < 1024)       b3[i] = bq[i];
    else if (i < 2048)  b3[i] = bk[i - 1024];
    else if (i < QKVN)  b3[i] = bv[i - 2048];
}

// ---------------- mma.sync bf16 GEMM ----------------
// C[m,n] = sum_{k'} A'[m,k'] * B'[n,k'] + bias[n],  K' = 3072 fixed.
// 128x128 CTA tile, BK=32, 4-stage cp.async pipeline, 8 warps (2x4), warp tile 64x32.
#define BM 128
#define BN 128
#define BK 32
#define STAGES 4
#define ATILE (BM*BK*2)              // 8192 B
#define SSTAGE (2*ATILE)             // 16384 B (A+B)
#define GSMEM (STAGES*SSTAGE)        // 65536 B
#define NCHUNK (KP/BK)               // 96

// swizzled smem address for (row, 16B-unit c16) in a [rows][32] bf16 tile (64B rows)
__device__ __forceinline__ uint32_t swz(uint32_t base, int r, int c16) {
    return base + r * 64 + ((c16 ^ ((r >> 1) & 3)) << 4);
}

__global__ __launch_bounds__(256, 2)
void gemm_bf16(const __nv_bfloat16* __restrict__ Ap, const __nv_bfloat16* __restrict__ Bp,
               const float* __restrict__ bias, float* __restrict__ C, int N)
{
    extern __shared__ char smem[];
    uint32_t sb = smem_u32(smem);
    int tid = threadIdx.x;
    int lane = tid & 31, wid = tid >> 5;
    int wm = wid >> 2, wn = wid & 3;         // 2 x 4 warp grid
    int row0 = blockIdx.x * BM;
    int col0 = blockIdx.y * BN;

    const __nv_bfloat16* Ag = Ap + (size_t)row0 * KP;
    const __nv_bfloat16* Bg = Bp + (size_t)col0 * KP;

    float acc[4][4][4];
#pragma unroll
    for (int i = 0; i < 4; i++)
#pragma unroll
        for (int j = 0; j < 4; j++)
#pragma unroll
            for (int q = 0; q < 4; q++) acc[i][j][q] = 0.f;

    // per-thread load slots: 2 A units + 2 B units per stage
    int u0 = tid * 2;
    int lr0 = u0 >> 2, lc0 = u0 & 3;
    int lr1 = (u0 + 1) >> 2, lc1 = (u0 + 1) & 3;

    // prologue: fill STAGES-1 stages
#pragma unroll
    for (int s = 0; s < STAGES - 1; s++) {
        uint32_t aB = sb + s * SSTAGE, bB = aB + ATILE;
        int k0 = s * BK;
        cp16(swz(aB, lr0, lc0), Ag + (size_t)lr0 * KP + k0 + lc0 * 8);
        cp16(swz(aB, lr1, lc1), Ag + (size_t)lr1 * KP + k0 + lc1 * 8);
        cp16(swz(bB, lr0, lc0), Bg + (size_t)lr0 * KP + k0 + lc0 * 8);
        cp16(swz(bB, lr1, lc1), Bg + (size_t)lr1 * KP + k0 + lc1 * 8);
        CP_COMMIT();
    }

    for (int kt = 0; kt < NCHUNK; kt++) {
        CP_WAIT(STAGES - 2);
        __syncthreads();

        int pf = kt + STAGES - 1;
        if (pf < NCHUNK) {
            int st = pf & (STAGES - 1);
            uint32_t aB = sb + st * SSTAGE, bB = aB + ATILE;
            int k0 = pf * BK;
            cp16(swz(aB, lr0, lc0), Ag + (size_t)lr0 * KP + k0 + lc0 * 8);
            cp16(swz(aB, lr1, lc1), Ag + (size_t)lr1 * KP + k0 + lc1 * 8);
            cp16(swz(bB, lr0, lc0), Bg + (size_t)lr0 * KP + k0 + lc0 * 8);
            cp16(swz(bB, lr1, lc1), Bg + (size_t)lr1 * KP + k0 + lc1 * 8);
        }
        CP_COMMIT();

        uint32_t aB = sb + (kt & (STAGES - 1)) * SSTAGE;
        uint32_t bB = aB + ATILE;
#pragma unroll
        for (int ks = 0; ks < 2; ks++) {
            uint32_t ra[4][4], rb[2][4];
#pragma unroll
            for (int mi = 0; mi < 4; mi++) {
                int r = wm * 64 + mi * 16 + (lane & 15);
                int c16 = ks * 2 + (lane >> 4);
                LDSM4(ra[mi][0], ra[mi][1], ra[mi][2], ra[mi][3], swz(aB, r, c16));
            }
#pragma unroll
            for (int ni = 0; ni < 2; ni++) {
                int r = wn * 32 + ni * 16 + (lane & 7) + ((lane >> 4) & 1) * 8;
                int c16 = ks * 2 + ((lane >> 3) & 1);
                LDSM4(rb[ni][0], rb[ni][1], rb[ni][2], rb[ni][3], swz(bB, r, c16));
            }
#pragma unroll
            for (int mi = 0; mi < 4; mi++)
#pragma unroll
                for (int nj = 0; nj < 4; nj++) {
                    uint32_t b0 = rb[nj >> 1][(nj & 1) * 2];
                    uint32_t b1 = rb[nj >> 1][(nj & 1) * 2 + 1];
                    MMA16816(acc[mi][nj], ra[mi], b0, b1);
                }
        }
    }

    // epilogue: thread owns (row = g + {0,8}, col = tg*2 + {0,1}) per frag
    int g = lane >> 2, tg = lane & 3;
#pragma unroll
    for (int mi = 0; mi < 4; mi++) {
        int r = row0 + wm * 64 + mi * 16 + g;
#pragma unroll
        for (int nj = 0; nj < 4; nj++) {
            int c = col0 + wn * 32 + nj * 8 + tg * 2;
            float bx = bias[c], by = bias[c + 1];
            float2 v0 = make_float2(acc[mi][nj][0] + bx, acc[mi][nj][1] + by);
            float2 v1 = make_float2(acc[mi][nj][2] + bx, acc[mi][nj][3] + by);
            *(float2*)(C + (size_t)r * N + c) = v0;
            *(float2*)(C + (size_t)(r + 8) * N + c) = v1;
        }
    }
}

// ---------------- attention (flash-style over fused qkv [M,3072]) ----------------
#define AT_BQ 128
#define AT_BS 64
__global__ __launch_bounds__(128)
void attn_kernel(const float* __restrict__ qkv, __nv_bfloat16* __restrict__ op)
{
    __shared__ float Ks[AT_BS][PD];
    __shared__ float Vs[AT_BS][PD];
    int bh = blockIdx.y;
    int tq = blockIdx.x * AT_BQ + threadIdx.x;
    int b = bh >> 4, h = bh & 15;

    const float* base = qkv + (size_t)b * PT * QKVN;
    const float* qrow = base + (size_t)tq * QKVN + h * PD;
    const float* kbase = base + 1024 + h * PD;
    const float* vbase = base + 2048 + h * PD;

    float qreg[PD];
#pragma unroll
    for (int i = 0; i < 16; i++) {
        float4 tv = ((const float4*)qrow)[i];
        qreg[4*i+0]=tv.x; qreg[4*i+1]=tv.y; qreg[4*i+2]=tv.z; qreg[4*i+3]=tv.w;
    }
    float m = -INFINITY, l = 0.f;
    float acc[PD];
#pragma unroll
    for (int d = 0; d < PD; d++) acc[d] = 0.f;

    int send = blockIdx.x * AT_BQ + AT_BQ - 1;
    for (int s0 = 0; s0 <= send; s0 += AT_BS) {
#pragma unroll
        for (int i = 0; i < 8; i++) {
            int f = threadIdx.x + i * 128;
            int r = f >> 4, c = f & 15;
            ((float4*)Ks[r])[c] = *(const float4*)(kbase + (size_t)(s0 + r) * QKVN + c * 4);
            ((float4*)Vs[r])[c] = *(const float4*)(vbase + (size_t)(s0 + r) * QKVN + c * 4);
        }
        __syncthreads();

        int smax = tq - s0 + 1;
        if (smax > AT_BS) smax = AT_BS;
        for (int s = 0; s < smax; s++) {
            float dot = 0.f;
            const float4* kr = (const float4*)Ks[s];
#pragma unroll
            for (int i = 0; i < 16; i++) {
                float4 kv = kr[i];
                dot += qreg[4*i+0]*kv.x + qreg[4*i+1]*kv.y
                     + qreg[4*i+2]*kv.z + qreg[4*i+3]*kv.w;
            }
            if (dot == 0.0f) continue;   // faithful masked_fill(w==0, -inf)
            if (dot > m) {
                float c = __expf(m - dot);
                l *= c;
#pragma unroll
                for (int d = 0; d < PD; d++) acc[d] *= c;
                m = dot;
            }
            float p = __expf(dot - m);
            l += p;
            const float4* vr = (const float4*)Vs[s];
#pragma unroll
            for (int i = 0; i < 16; i++) {
                float4 vv = vr[i];
                acc[4*i+0] += p * vv.x; acc[4*i+1] += p * vv.y;
                acc[4*i+2] += p * vv.z; acc[4*i+3] += p * vv.w;
            }
        }
        __syncthreads();
    }

    float inv = 1.f / (l * 8.0f);     // post-softmax 1/sqrt(64)
    size_t orow = (size_t)(b * PT + tq) * KP + h * PD;
#pragma unroll
    for (int d = 0; d < PD; d++) {
        float v = acc[d] * inv;
        __nv_bfloat16 hh = __float2bfloat16(v);
        __nv_bfloat16 ll = __float2bfloat16(v - __bfloat162float(hh));
        op[orow + d] = hh;                // A-layout [h|h|l]
        op[orow + 1024 + d] = hh;
        op[orow + 2048 + d] = ll;
    }
}

// ---------------- loss ----------------
__global__ __launch_bounds__(256)
void rowloss_kernel(const float* __restrict__ logits, const int* __restrict__ targets,
                    float* __restrict__ rowloss)
{
    __shared__ float red[256];
    int row = blockIdx.x, tid = threadIdx.x;
    const float* lr = logits + (size_t)row * PV;
    float mx = -INFINITY;
    for (int c = tid; c < PV; c += 256) mx = fmaxf(mx, lr[c]);
    red[tid] = mx; __syncthreads();
    for (int s = 128; s > 0; s >>= 1) { if (tid < s) red[tid] = fmaxf(red[tid], red[tid+s]); __syncthreads(); }
    mx = red[0]; __syncthreads();
    float se = 0.f;
    for (int c = tid; c < PV; c += 256) se += expf(lr[c] - mx);
    red[tid] = se; __syncthreads();
    for (int s = 128; s > 0; s >>= 1) { if (tid < s) red[tid] += red[tid+s]; __syncthreads(); }
    if (tid == 0) rowloss[row] = -(lr[targets[row]] - (mx + logf(red[0])));
}

__global__ __launch_bounds__(256)
void finloss_kernel(const float* __restrict__ rowloss, float* __restrict__ out_loss)
{
    __shared__ float red[256];
    int tid = threadIdx.x;
    float s = 0.f;
    for (int i = tid; i < PM; i += 256) s += rowloss[i];
    red[tid] = s; __syncthreads();
    for (int k = 128; k > 0; k >>= 1) { if (tid < k) red[tid] += red[tid+k]; __syncthreads(); }
    if (tid == 0) out_loss[0] = red[0] / (float)PM;
}

// ---------------- launch ----------------
extern "C" void kernel_launch(void* const* d_in, const int* in_sizes, int n_in,
                              void* d_out, int out_size)
{
    const int*   tokens    = (const int*)d_in[0];
    const int*   targets   = (const int*)d_in[1];
    const float* tok_table = (const float*)d_in[2];
    const float* pos_emb   = (const float*)d_in[3];
    const float* Wq = (const float*)d_in[4];  const float* bq = (const float*)d_in[5];
    const float* Wk = (const float*)d_in[6];  const float* bk = (const float*)d_in[7];
    const float* Wv = (const float*)d_in[8];  const float* bv = (const float*)d_in[9];
    const float* Wo = (const float*)d_in[10]; const float* bo = (const float*)d_in[11];
    float* out = (float*)d_out;

    __nv_bfloat16 *xp, *wqkv, *wop, *op;
    float *qkv, *b3, *rl;
    cudaGetSymbolAddress((void**)&xp,   g_xp);
    cudaGetSymbolAddress((void**)&wqkv, g_wqkv);
    cudaGetSymbolAddress((void**)&wop,  g_wop);
    cudaGetSymbolAddress((void**)&op,   g_op);
    cudaGetSymbolAddress((void**)&qkv,  g_qkv);
    cudaGetSymbolAddress((void**)&b3,   g_bias3);
    cudaGetSymbolAddress((void**)&rl,   g_rowloss);

    cudaFuncSetAttribute(gemm_bf16, cudaFuncAttributeMaxDynamicSharedMemorySize, GSMEM);

    // 1) embed + A-split
    embed_split<<<(PM * PE) / 256, 256>>>(tokens, tok_table, pos_emb, xp);

    // 2) weight B-splits (+ bias pack)
    splitB<<<(PE*PE)/256, 256>>>(Wq, wqkv,                     PE*PE);
    splitB<<<(PE*PE)/256, 256>>>(Wk, wqkv + (size_t)1024*KP,   PE*PE);
    splitB<<<(PE*PE)/256, 256>>>(Wv, wqkv + (size_t)2048*KP,   PE*PE);
    splitB<<<(int)(((size_t)PV*PE)/256), 256>>>(Wo, wop, (int)((size_t)PV*PE));
    pack_bias<<<QKVN/256, 256>>>(bq, bk, bv, b3);

    // 3) fused QKV GEMM: [4096,3072'] x [3072,3072']^T
    gemm_bf16<<<dim3(PM/BM, QKVN/BN), 256, GSMEM>>>(xp, wqkv, b3, qkv, QKVN);

    // 4) attention -> o' (A-split layout)
    attn_kernel<<<dim3(PT/AT_BQ, PB*PH), AT_BQ>>>(qkv, op);

    // 5) logits GEMM: [4096,3072'] x [32000,3072']^T -> d_out
    gemm_bf16<<<dim3(PM/BM, PV/BN), 256, GSMEM>>>(op, wop, bo, out, PV);

    // 6) loss
    if ((size_t)out_size > BTV) {
        rowloss_kernel<<<PM, 256>>>(out, targets, rl);
        finloss_kernel<<<1, 256>>>(rl, out + BTV);
    }
}

// round 5
// speedup vs baseline: 3.0606x; 2.3461x over previous
#include <cuda_runtime.h>
#include <cuda_fp16.h>
#include <math.h>
#include <cstdint>

// ---------------- problem constants ----------------
#define PB 2
#define PT 2048
#define PE 1024
#define PH 16
#define PD 64
#define PV 32000
#define PM (PB*PT)            // 4096
#define QKVN 3072
#define BTV ((size_t)PM*PV)

// ---------------- scratch (__device__ globals) ----------------
__device__ __half g_xh[(size_t)PM*PE],  g_xl[(size_t)PM*PE];    // x hi/lo fp16
__device__ __half g_wqkv[(size_t)QKVN*PE];                       // Wq|Wk|Wv fp16
__device__ __half g_wo[(size_t)PV*PE];                           // Wo fp16
__device__ __half g_oh[(size_t)PM*PE],  g_ol[(size_t)PM*PE];    // attn out hi/lo
__device__ float  g_qkv[(size_t)PM*QKVN];                        // fused qkv (fp32)
__device__ float  g_bias3[QKVN];
__device__ float  g_rowloss[PM];

// ---------------- helpers ----------------
__device__ __forceinline__ uint32_t smem_u32(const void* p) {
    uint32_t a;
    asm("{ .reg .u64 t; cvta.to.shared.u64 t, %1; cvt.u32.u64 %0, t; }" : "=r"(a) : "l"(p));
    return a;
}
__device__ __forceinline__ void cp16(uint32_t dst, const void* src) {
    asm volatile("cp.async.cg.shared.global [%0], [%1], 16;" :: "r"(dst), "l"(src) : "memory");
}
#define CP_COMMIT() asm volatile("cp.async.commit_group;" ::: "memory")
#define CP_WAIT(n)  asm volatile("cp.async.wait_group %0;" :: "n"(n) : "memory")

#define LDSM4(r0,r1,r2,r3,addr) \
    asm volatile("ldmatrix.sync.aligned.m8n8.x4.shared.b16 {%0,%1,%2,%3}, [%4];" \
        : "=r"(r0),"=r"(r1),"=r"(r2),"=r"(r3) : "r"(addr))

#define MMAF16(c, a, b0, b1) \
    asm volatile("mma.sync.aligned.m16n8k16.row.col.f32.f16.f16.f32 " \
        "{%0,%1,%2,%3}, {%4,%5,%6,%7}, {%8,%9}, {%0,%1,%2,%3};" \
        : "+f"((c)[0]), "+f"((c)[1]), "+f"((c)[2]), "+f"((c)[3]) \
        : "r"((a)[0]), "r"((a)[1]), "r"((a)[2]), "r"((a)[3]), "r"(b0), "r"(b1))

// ---------------- embed + fp16 hi/lo split of x ----------------
__global__ void embed_split(const int* __restrict__ tokens,
                            const float* __restrict__ tok_table,
                            const float* __restrict__ pos_emb,
                            __half* __restrict__ xh, __half* __restrict__ xl)
{
    int idx = blockIdx.x * blockDim.x + threadIdx.x; // over M*E
    int row = idx >> 10, e = idx & (PE - 1);
    int t = row & (PT - 1);
    float v = tok_table[(size_t)tokens[row] * PE + e] + pos_emb[(size_t)t * PE + e];
    __half h = __float2half(v);
    xh[idx] = h;
    xl[idx] = __float2half(v - __half2float(h));
}

// plain fp32 -> fp16 convert
__global__ void convW(const float* __restrict__ src, __half* __restrict__ dst, int n)
{
    int idx = blockIdx.x * blockDim.x + threadIdx.x;
    if (idx < n) dst[idx] = __float2half(src[idx]);
}

__global__ void pack_bias(const float* __restrict__ bq, const float* __restrict__ bk,
                          const float* __restrict__ bv, float* __restrict__ b3)
{
    int i = blockIdx.x * blockDim.x + threadIdx.x;
    if (i < 1024)       b3[i] = bq[i];
    else if (i < 2048)  b3[i] = bk[i - 1024];
    else if (i < QKVN)  b3[i] = bv[i - 2048];
}

// ---------------- fp16 split-A GEMM via mma.sync ----------------
// C[m,n] = sum_k (Ah[m,k]+Al[m,k]) * B[n,k] + bias[n],  K = 1024.
// 128x128 CTA tile, BK=32, 4-stage cp.async pipeline, 8 warps (2x4), warp tile 64x32.
// Per chunk: load Ah,Al,B tiles; issue MMAs for both A planes against shared B frags.
#define BM 128
#define BN 128
#define BK 32
#define KE 1024
#define STAGES 4
#define TILE_B (BM*BK*2)             // 8192 B per plane tile
#define SSTAGE (3*TILE_B)            // 24576 B (Ah+Al+B)
#define GSMEM (STAGES*SSTAGE)        // 98304 B
#define NCHUNK (KE/BK)               // 32

// swizzled smem addr for (row, 16B-unit c16) in a [rows][32] fp16 tile (64B rows)
__device__ __forceinline__ uint32_t swz(uint32_t base, int r, int c16) {
    return base + r * 64 + ((c16 ^ ((r >> 1) & 3)) << 4);
}

__global__ __launch_bounds__(256, 2)
void gemm_fp16(const __half* __restrict__ Ah, const __half* __restrict__ Al,
               const __half* __restrict__ Bw,
               const float* __restrict__ bias, float* __restrict__ C, int N)
{
    extern __shared__ char smem[];
    uint32_t sb = smem_u32(smem);
    int tid = threadIdx.x;
    int lane = tid & 31, wid = tid >> 5;
    int wm = wid >> 2, wn = wid & 3;         // 2 x 4 warp grid
    int row0 = blockIdx.x * BM;
    int col0 = blockIdx.y * BN;

    const __half* Ahg = Ah + (size_t)row0 * KE;
    const __half* Alg = Al + (size_t)row0 * KE;
    const __half* Bg  = Bw + (size_t)col0 * KE;

    float acc[4][4][4];
#pragma unroll
    for (int i = 0; i < 4; i++)
#pragma unroll
        for (int j = 0; j < 4; j++)
#pragma unroll
            for (int q = 0; q < 4; q++) acc[i][j][q] = 0.f;

    // per-stage loads: 3 planes x 512 16B-units = 1536 units / 256 thr = 6 per thread
    // unit = tid + 256*j ; plane p = unit>>9 ; idx = unit&511 ; r = idx>>2 ; c16 = idx&3
#define STAGE_LOAD(stageBase, k0)                                              \
    do {                                                                       \
        _Pragma("unroll")                                                      \
        for (int j = 0; j < 6; j++) {                                          \
            int u = tid + 256 * j;                                             \
            int p = u >> 9, ix = u & 511;                                      \
            int r = ix >> 2, c16 = ix & 3;                                     \
            const __half* src = (p == 0 ? Ahg : (p == 1 ? Alg : Bg));          \
            cp16(swz(sb + (stageBase), r, c16) + p * TILE_B,                   \
                 src + (size_t)r * KE + (k0) + c16 * 8);                       \
        }                                                                      \
    } while (0)

    // prologue: fill STAGES-1 stages
#pragma unroll
    for (int s = 0; s < STAGES - 1; s++) {
        STAGE_LOAD(s * SSTAGE, s * BK);
        CP_COMMIT();
    }

    for (int kt = 0; kt < NCHUNK; kt++) {
        CP_WAIT(STAGES - 2);
        __syncthreads();

        int pf = kt + STAGES - 1;
        if (pf < NCHUNK) {
            int st = pf & (STAGES - 1);
            STAGE_LOAD(st * SSTAGE, pf * BK);
        }
        CP_COMMIT();

        uint32_t stB = sb + (kt & (STAGES - 1)) * SSTAGE;
        uint32_t aHB = stB, aLB = stB + TILE_B, bB = stB + 2 * TILE_B;
#pragma unroll
        for (int ks = 0; ks < 2; ks++) {
            uint32_t rb[2][4];
#pragma unroll
            for (int ni = 0; ni < 2; ni++) {
                int r = wn * 32 + ni * 16 + (lane & 7) + ((lane >> 4) & 1) * 8;
                int c16 = ks * 2 + ((lane >> 3) & 1);
                LDSM4(rb[ni][0], rb[ni][1], rb[ni][2], rb[ni][3], swz(bB, r, c16));
            }
            int ar = wm * 64 + (lane & 15);
            int ac16 = ks * 2 + (lane >> 4);
            // plane hi
            {
                uint32_t ra[4][4];
#pragma unroll
                for (int mi = 0; mi < 4; mi++)
                    LDSM4(ra[mi][0], ra[mi][1], ra[mi][2], ra[mi][3],
                          swz(aHB, ar + mi * 16, ac16));
#pragma unroll
                for (int mi = 0; mi < 4; mi++)
#pragma unroll
                    for (int nj = 0; nj < 4; nj++)
                        MMAF16(acc[mi][nj], ra[mi],
                               rb[nj >> 1][(nj & 1) * 2], rb[nj >> 1][(nj & 1) * 2 + 1]);
            }
            // plane lo
            {
                uint32_t ra[4][4];
#pragma unroll
                for (int mi = 0; mi < 4; mi++)
                    LDSM4(ra[mi][0], ra[mi][1], ra[mi][2], ra[mi][3],
                          swz(aLB, ar + mi * 16, ac16));
#pragma unroll
                for (int mi = 0; mi < 4; mi++)
#pragma unroll
                    for (int nj = 0; nj < 4; nj++)
                        MMAF16(acc[mi][nj], ra[mi],
                               rb[nj >> 1][(nj & 1) * 2], rb[nj >> 1][(nj & 1) * 2 + 1]);
            }
        }
    }

    // epilogue
    int g = lane >> 2, tg = lane & 3;
#pragma unroll
    for (int mi = 0; mi < 4; mi++) {
        int r = row0 + wm * 64 + mi * 16 + g;
#pragma unroll
        for (int nj = 0; nj < 4; nj++) {
            int c = col0 + wn * 32 + nj * 8 + tg * 2;
            float bx = bias[c], by = bias[c + 1];
            float2 v0 = make_float2(acc[mi][nj][0] + bx, acc[mi][nj][1] + by);
            float2 v1 = make_float2(acc[mi][nj][2] + bx, acc[mi][nj][3] + by);
            *(float2*)(C + (size_t)r * N + c) = v0;
            *(float2*)(C + (size_t)(r + 8) * N + c) = v1;
        }
    }
}

// ---------------- attention (flash-style over fused qkv [M,3072]) ----------------
#define AT_BQ 128
#define AT_BS 64
__global__ __launch_bounds__(128)
void attn_kernel(const float* __restrict__ qkv,
                 __half* __restrict__ oh, __half* __restrict__ ol)
{
    __shared__ float Ks[AT_BS][PD];
    __shared__ float Vs[AT_BS][PD];
    int bh = blockIdx.y;
    int tq = blockIdx.x * AT_BQ + threadIdx.x;
    int b = bh >> 4, h = bh & 15;

    const float* base = qkv + (size_t)b * PT * QKVN;
    const float* qrow = base + (size_t)tq * QKVN + h * PD;
    const float* kbase = base + 1024 + h * PD;
    const float* vbase = base + 2048 + h * PD;

    float qreg[PD];
#pragma unroll
    for (int i = 0; i < 16; i++) {
        float4 tv = ((const float4*)qrow)[i];
        qreg[4*i+0]=tv.x; qreg[4*i+1]=tv.y; qreg[4*i+2]=tv.z; qreg[4*i+3]=tv.w;
    }
    float m = -INFINITY, l = 0.f;
    float acc[PD];
#pragma unroll
    for (int d = 0; d < PD; d++) acc[d] = 0.f;

    int send = blockIdx.x * AT_BQ + AT_BQ - 1;
    for (int s0 = 0; s0 <= send; s0 += AT_BS) {
#pragma unroll
        for (int i = 0; i < 8; i++) {
            int f = threadIdx.x + i * 128;
            int r = f >> 4, c = f & 15;
            ((float4*)Ks[r])[c] = *(const float4*)(kbase + (size_t)(s0 + r) * QKVN + c * 4);
            ((float4*)Vs[r])[c] = *(const float4*)(vbase + (size_t)(s0 + r) * QKVN + c * 4);
        }
        __syncthreads();

        int smax = tq - s0 + 1;
        if (smax > AT_BS) smax = AT_BS;
        for (int s = 0; s < smax; s++) {
            float dot = 0.f;
            const float4* kr = (const float4*)Ks[s];
#pragma unroll
            for (int i = 0; i < 16; i++) {
                float4 kv = kr[i];
                dot += qreg[4*i+0]*kv.x + qreg[4*i+1]*kv.y
                     + qreg[4*i+2]*kv.z + qreg[4*i+3]*kv.w;
            }
            if (dot == 0.0f) continue;   // faithful masked_fill(w==0, -inf)
            if (dot > m) {
                float c = __expf(m - dot);
                l *= c;
#pragma unroll
                for (int d = 0; d < PD; d++) acc[d] *= c;
                m = dot;
            }
            float p = __expf(dot - m);
            l += p;
            const float4* vr = (const float4*)Vs[s];
#pragma unroll
            for (int i = 0; i < 16; i++) {
                float4 vv = vr[i];
                acc[4*i+0] += p * vv.x; acc[4*i+1] += p * vv.y;
                acc[4*i+2] += p * vv.z; acc[4*i+3] += p * vv.w;
            }
        }
        __syncthreads();
    }

    float inv = 1.f / (l * 8.0f);     // post-softmax 1/sqrt(64)
    size_t orow = (size_t)(b * PT + tq) * PE + h * PD;
#pragma unroll
    for (int d = 0; d < PD; d++) {
        float v = acc[d] * inv;
        __half hh = __float2half(v);
        oh[orow + d] = hh;
        ol[orow + d] = __float2half(v - __half2float(hh));
    }
}

// ---------------- loss: single-pass online log-softmax ----------------
__global__ __launch_bounds__(256)
void rowloss_kernel(const float* __restrict__ logits, const int* __restrict__ targets,
                    float* __restrict__ rowloss)
{
    __shared__ float sm[256], ss[256];
    int row = blockIdx.x, tid = threadIdx.x;
    const float* lr = logits + (size_t)row * PV;

    float m = -INFINITY, s = 0.f;
    for (int c = tid; c < PV; c += 256) {
        float v = lr[c];
        if (v > m) { s *= __expf(m - v); m = v; }
        s += __expf(v - m);
    }
    sm[tid] = m; ss[tid] = s; __syncthreads();
    for (int k = 128; k > 0; k >>= 1) {
        if (tid < k) {
            float m1 = sm[tid], s1 = ss[tid], m2 = sm[tid + k], s2 = ss[tid + k];
            float mm = fmaxf(m1, m2);
            sm[tid] = mm;
            ss[tid] = s1 * __expf(m1 - mm) + s2 * __expf(m2 - mm);
        }
        __syncthreads();
    }
    if (tid == 0) {
        float lse = sm[0] + logf(ss[0]);
        rowloss[row] = -(lr[targets[row]] - lse);
    }
}

__global__ __launch_bounds__(256)
void finloss_kernel(const float* __restrict__ rowloss, float* __restrict__ out_loss)
{
    __shared__ float red[256];
    int tid = threadIdx.x;
    float s = 0.f;
    for (int i = tid; i < PM; i += 256) s += rowloss[i];
    red[tid] = s; __syncthreads();
    for (int k = 128; k > 0; k >>= 1) { if (tid < k) red[tid] += red[tid+k]; __syncthreads(); }
    if (tid == 0) out_loss[0] = red[0] / (float)PM;
}

// ---------------- launch ----------------
extern "C" void kernel_launch(void* const* d_in, const int* in_sizes, int n_in,
                              void* d_out, int out_size)
{
    const int*   tokens    = (const int*)d_in[0];
    const int*   targets   = (const int*)d_in[1];
    const float* tok_table = (const float*)d_in[2];
    const float* pos_emb   = (const float*)d_in[3];
    const float* Wq = (const float*)d_in[4];  const float* bq = (const float*)d_in[5];
    const float* Wk = (const float*)d_in[6];  const float* bk = (const float*)d_in[7];
    const float* Wv = (const float*)d_in[8];  const float* bv = (const float*)d_in[9];
    const float* Wo = (const float*)d_in[10]; const float* bo = (const float*)d_in[11];
    float* out = (float*)d_out;

    __half *xh, *xl, *wqkv, *wo, *oh, *ol;
    float *qkv, *b3, *rl;
    cudaGetSymbolAddress((void**)&xh,   g_xh);
    cudaGetSymbolAddress((void**)&xl,   g_xl);
    cudaGetSymbolAddress((void**)&wqkv, g_wqkv);
    cudaGetSymbolAddress((void**)&wo,   g_wo);
    cudaGetSymbolAddress((void**)&oh,   g_oh);
    cudaGetSymbolAddress((void**)&ol,   g_ol);
    cudaGetSymbolAddress((void**)&qkv,  g_qkv);
    cudaGetSymbolAddress((void**)&b3,   g_bias3);
    cudaGetSymbolAddress((void**)&rl,   g_rowloss);

    cudaFuncSetAttribute(gemm_fp16, cudaFuncAttributeMaxDynamicSharedMemorySize, GSMEM);

    // 1) embed + fp16 hi/lo split of x
    embed_split<<<(PM * PE) / 256, 256>>>(tokens, tok_table, pos_emb, xh, xl);

    // 2) weight converts (single fp16) + bias pack
    convW<<<(PE*PE)/256, 256>>>(Wq, wqkv,                  PE*PE);
    convW<<<(PE*PE)/256, 256>>>(Wk, wqkv + (size_t)PE*PE,  PE*PE);
    convW<<<(PE*PE)/256, 256>>>(Wv, wqkv + (size_t)2*PE*PE, PE*PE);
    convW<<<(int)(((size_t)PV*PE)/256), 256>>>(Wo, wo, (int)((size_t)PV*PE));
    pack_bias<<<QKVN/256, 256>>>(bq, bk, bv, b3);

    // 3) fused QKV GEMM: [4096,1024] x [3072,1024]^T (split-A fp16)
    gemm_fp16<<<dim3(PM/BM, QKVN/BN), 256, GSMEM>>>(xh, xl, wqkv, b3, qkv, QKVN);

    // 4) attention -> oh/ol fp16 planes
    attn_kernel<<<dim3(PT/AT_BQ, PB*PH), AT_BQ>>>(qkv, oh, ol);

    // 5) logits GEMM: [4096,1024] x [32000,1024]^T -> d_out
    gemm_fp16<<<dim3(PM/BM, PV/BN), 256, GSMEM>>>(oh, ol, wo, bo, out, PV);

    // 6) loss
    if ((size_t)out_size > BTV) {
        rowloss_kernel<<<PM, 256>>>(out, targets, rl);
        finloss_kernel<<<1, 256>>>(rl, out + BTV);
    }
}